// round 2
// baseline (speedup 1.0000x reference)
#include <cuda_runtime.h>
#include <math.h>

#define NMAX 100000
#define EMAX 1600000
#define D 64
#define KDIM 192
#define OUTC 64

// ---- scratch (static device allocations are the only legal scratch) ----
__device__ int   g_cnt[NMAX];
__device__ int   g_start[NMAX + 1];
__device__ int   g_cursor[NMAX];
__device__ int   g_adj[EMAX];
__device__ float g_comb[(size_t)NMAX * KDIM];   // [N, 192] sum|max|min

// ---------------- CSR build ----------------

__global__ void zero_cnt_kernel(int n) {
    int i = blockIdx.x * blockDim.x + threadIdx.x;
    if (i < n) g_cnt[i] = 0;
}

__global__ void hist_kernel(const int* __restrict__ row, int E) {
    int i = blockIdx.x * blockDim.x + threadIdx.x;
    if (i < E) atomicAdd(&g_cnt[row[i]], 1);
}

// single-block exclusive scan over g_cnt -> g_start, g_cursor
__global__ void scan_kernel(int n) {
    __shared__ int warp_sums[32];
    __shared__ int s_carry;
    int tid = threadIdx.x;
    int lane = tid & 31, wid = tid >> 5;
    if (tid == 0) s_carry = 0;
    __syncthreads();
    int chunks = (n + 1023) / 1024;
    for (int c = 0; c < chunks; c++) {
        int i = c * 1024 + tid;
        int v = (i < n) ? g_cnt[i] : 0;
        // warp inclusive scan
        int x = v;
        #pragma unroll
        for (int o = 1; o < 32; o <<= 1) {
            int y = __shfl_up_sync(0xffffffffu, x, o);
            if (lane >= o) x += y;
        }
        if (lane == 31) warp_sums[wid] = x;
        __syncthreads();
        if (wid == 0) {
            int w = warp_sums[lane];
            #pragma unroll
            for (int o = 1; o < 32; o <<= 1) {
                int y = __shfl_up_sync(0xffffffffu, w, o);
                if (lane >= o) w += y;
            }
            warp_sums[lane] = w;
        }
        __syncthreads();
        int incl = x + (wid > 0 ? warp_sums[wid - 1] : 0) + s_carry;
        int excl = incl - v;
        if (i < n) { g_start[i] = excl; g_cursor[i] = excl; }
        __syncthreads();              // everyone done reading s_carry/warp_sums
        if (tid == 1023) s_carry = incl;
        __syncthreads();
    }
    if (tid == 0) g_start[n] = s_carry;
}

__global__ void scatter_kernel(const int* __restrict__ row,
                               const int* __restrict__ col, int E) {
    int i = blockIdx.x * blockDim.x + threadIdx.x;
    if (i < E) {
        int p = atomicAdd(&g_cursor[row[i]], 1);
        g_adj[p] = col[i];
    }
}

// ---------------- aggregation: warp per node ----------------
// each lane owns 2 feature dims; reads features[col] as float2 (coalesced 256B/warp)

__global__ void aggregate_kernel(const float* __restrict__ feat, int n) {
    int tid  = blockIdx.x * blockDim.x + threadIdx.x;
    int node = tid >> 5;
    int lane = tid & 31;
    if (node >= n) return;

    int s = g_start[node];
    int e = g_start[node + 1];

    float sx = 0.f, sy = 0.f;
    float mxx = -INFINITY, mxy = -INFINITY;
    float mnx =  INFINITY, mny =  INFINITY;

    for (int j = s; j < e; j++) {
        int c = g_adj[j];                       // broadcast load
        float2 f = *(const float2*)&feat[(size_t)c * D + 2 * lane];
        sx += f.x;  sy += f.y;
        mxx = fmaxf(mxx, f.x);  mxy = fmaxf(mxy, f.y);
        mnx = fminf(mnx, f.x);  mny = fminf(mny, f.y);
    }
    if (e == s) { mxx = mxy = 0.f; mnx = mny = 0.f; }

    float* cb = &g_comb[(size_t)node * KDIM];
    *(float2*)&cb[        2 * lane] = make_float2(sx,  sy);
    *(float2*)&cb[ D  +   2 * lane] = make_float2(mxx, mxy);
    *(float2*)&cb[2*D +   2 * lane] = make_float2(mnx, mny);
}

// ---------------- MLP: tiled FP32 GEMM [N,192] x [192,64] + bias, tanh ----------------
// BM=128, BN=64 (full width), BK=16, 256 threads, 8x4 register tile per thread.
// A is read from the __device__ symbol g_comb directly (host code must NOT take
// the address of a __device__ variable — that was the round-1 bug).

#define BM 128
#define BK 16
#define BN 64

__global__ __launch_bounds__(256) void mlp_gemm_kernel(
    const float* __restrict__ Wg,     // [192,64]
    const float* __restrict__ bg,     // [64]
    float* __restrict__ out, int n)
{
    __shared__ float As[BK][BM];      // 8KB, stored k-major for column reads
    __shared__ float Bs[BK][BN];      // 4KB

    const float* __restrict__ A = g_comb;

    int tid = threadIdx.x;
    int block_m = blockIdx.x * BM;
    int tx = tid & 15;                // output-col group (4 cols)
    int ty = tid >> 4;                // output-row group (8 rows)

    // A tile load mapping: 128x16 floats = 2 float4 per thread
    int a_row  = tid >> 2;            // 0..63
    int a_col4 = (tid & 3) * 4;       // 0,4,8,12
    // B tile load mapping: 16x64 floats = 1 float4 per thread
    int b_row  = tid >> 4;            // 0..15
    int b_col4 = (tid & 15) * 4;

    float acc[8][4];
    #pragma unroll
    for (int i = 0; i < 8; i++)
        #pragma unroll
        for (int j = 0; j < 4; j++) acc[i][j] = 0.f;

    for (int k0 = 0; k0 < KDIM; k0 += BK) {
        #pragma unroll
        for (int r = 0; r < 2; r++) {
            int m  = a_row + r * 64;
            int gm = block_m + m;
            float4 v = make_float4(0.f, 0.f, 0.f, 0.f);
            if (gm < n) v = *(const float4*)&A[(size_t)gm * KDIM + k0 + a_col4];
            As[a_col4 + 0][m] = v.x;
            As[a_col4 + 1][m] = v.y;
            As[a_col4 + 2][m] = v.z;
            As[a_col4 + 3][m] = v.w;
        }
        *(float4*)&Bs[b_row][b_col4] =
            *(const float4*)&Wg[(size_t)(k0 + b_row) * BN + b_col4];
        __syncthreads();

        #pragma unroll
        for (int k = 0; k < BK; k++) {
            float ra[8], rb[4];
            #pragma unroll
            for (int i = 0; i < 8; i++) ra[i] = As[k][ty * 8 + i];
            #pragma unroll
            for (int j = 0; j < 4; j++) rb[j] = Bs[k][tx * 4 + j];
            #pragma unroll
            for (int i = 0; i < 8; i++)
                #pragma unroll
                for (int j = 0; j < 4; j++)
                    acc[i][j] += ra[i] * rb[j];
        }
        __syncthreads();
    }

    float4 bv = *(const float4*)&bg[tx * 4];
    #pragma unroll
    for (int i = 0; i < 8; i++) {
        int gm = block_m + ty * 8 + i;
        if (gm < n) {
            float4 o;
            o.x = tanhf(acc[i][0] + bv.x);
            o.y = tanhf(acc[i][1] + bv.y);
            o.z = tanhf(acc[i][2] + bv.z);
            o.w = tanhf(acc[i][3] + bv.w);
            *(float4*)&out[(size_t)gm * OUTC + tx * 4] = o;
        }
    }
}

// ---------------- launch ----------------

extern "C" void kernel_launch(void* const* d_in, const int* in_sizes, int n_in,
                              void* d_out, int out_size) {
    const int*   row  = (const int*)d_in[0];
    const int*   col  = (const int*)d_in[1];
    const float* feat = (const float*)d_in[2];
    const float* W    = (const float*)d_in[3];
    const float* b    = (const float*)d_in[4];
    float* out = (float*)d_out;

    int E = in_sizes[0];
    int N = in_sizes[2] / D;

    zero_cnt_kernel<<<(N + 255) / 256, 256>>>(N);
    hist_kernel<<<(E + 255) / 256, 256>>>(row, E);
    scan_kernel<<<1, 1024>>>(N);
    scatter_kernel<<<(E + 255) / 256, 256>>>(row, col, E);
    aggregate_kernel<<<(N + 7) / 8, 256>>>(feat, N);
    mlp_gemm_kernel<<<(N + BM - 1) / BM, 256>>>(W, b, out, N);
}

// round 3
// speedup vs baseline: 1.4246x; 1.4246x over previous
#include <cuda_runtime.h>
#include <math.h>

#define NMAX 100000
#define EMAX 1600000
#define D 64
#define KDIM 192
#define OUTC 64

typedef unsigned long long u64;

// ---- scratch ----
__device__ int   g_cnt[NMAX];
__device__ int   g_start[NMAX + 1];
__device__ int   g_cursor[NMAX];
__device__ int   g_adj[EMAX];
__device__ int   g_bsum[260];
__device__ int   g_total;
__device__ float g_comb[(size_t)NMAX * KDIM];   // [N, 192] sum|max|min

// ---------------- CSR build ----------------

__global__ void zero_cnt_kernel(int n) {
    int i = blockIdx.x * blockDim.x + threadIdx.x;
    if (i < n) g_cnt[i] = 0;
}

__global__ void hist_kernel(const int* __restrict__ row, int E) {
    int i = blockIdx.x * blockDim.x + threadIdx.x;
    if (i < E) atomicAdd(&g_cnt[row[i]], 1);
}

// ---- hierarchical scan: SCAN_B=512 per block ----
#define SCAN_B 512

__global__ __launch_bounds__(SCAN_B) void scan_partial_kernel(int n) {
    __shared__ int ws[16];
    int blk = blockIdx.x, tid = threadIdx.x;
    int i = blk * SCAN_B + tid;
    int v = (i < n) ? g_cnt[i] : 0;
    int lane = tid & 31, wid = tid >> 5;
    int x = v;
    #pragma unroll
    for (int o = 1; o < 32; o <<= 1) {
        int y = __shfl_up_sync(0xffffffffu, x, o);
        if (lane >= o) x += y;
    }
    if (lane == 31) ws[wid] = x;
    __syncthreads();
    if (wid == 0 && lane < 16) {
        int w = ws[lane];
        #pragma unroll
        for (int o = 1; o < 16; o <<= 1) {
            int y = __shfl_up_sync(0x0000ffffu, w, o);
            if (lane >= o) w += y;
        }
        ws[lane] = w;
    }
    __syncthreads();
    int incl = x + (wid > 0 ? ws[wid - 1] : 0);
    if (i < n) g_start[i] = incl - v;          // block-local exclusive
    if (tid == SCAN_B - 1) g_bsum[blk] = incl; // block total
}

__global__ __launch_bounds__(256) void scan_bsums_kernel(int nb) {
    __shared__ int ws[8];
    int tid = threadIdx.x;
    int v = (tid < nb) ? g_bsum[tid] : 0;
    int lane = tid & 31, wid = tid >> 5;
    int x = v;
    #pragma unroll
    for (int o = 1; o < 32; o <<= 1) {
        int y = __shfl_up_sync(0xffffffffu, x, o);
        if (lane >= o) x += y;
    }
    if (lane == 31) ws[wid] = x;
    __syncthreads();
    if (wid == 0 && lane < 8) {
        int w = ws[lane];
        #pragma unroll
        for (int o = 1; o < 8; o <<= 1) {
            int y = __shfl_up_sync(0x000000ffu, w, o);
            if (lane >= o) w += y;
        }
        ws[lane] = w;
    }
    __syncthreads();
    int incl = x + (wid > 0 ? ws[wid - 1] : 0);
    g_bsum[tid] = incl - v;                    // exclusive block offsets
    if (tid == 255) g_total = incl;
}

__global__ __launch_bounds__(SCAN_B) void scan_add_kernel(int n) {
    int i = blockIdx.x * SCAN_B + threadIdx.x;
    if (i < n) {
        int s = g_start[i] + g_bsum[blockIdx.x];
        g_start[i] = s;
        g_cursor[i] = s;
    }
    if (i == 0) g_start[n] = g_total;
}

__global__ void scatter_kernel(const int* __restrict__ row,
                               const int* __restrict__ col, int E) {
    int i = blockIdx.x * blockDim.x + threadIdx.x;
    if (i < E) {
        int p = atomicAdd(&g_cursor[row[i]], 1);
        g_adj[p] = col[i];
    }
}

// ---------------- aggregation: HALF-warp per node, float4 per lane ----------------
// 16 lanes x float4 = 64 dims. 2-edge unroll gives MLP=2 on the gather chain.

__global__ __launch_bounds__(256) void aggregate_kernel(const float* __restrict__ feat, int n) {
    int gt   = blockIdx.x * blockDim.x + threadIdx.x;
    int node = gt >> 4;
    int lane = gt & 15;
    if (node >= n) return;

    int s = g_start[node];
    int e = g_start[node + 1];

    float4 sm = make_float4(0.f, 0.f, 0.f, 0.f);
    float4 mx = make_float4(-INFINITY, -INFINITY, -INFINITY, -INFINITY);
    float4 mn = make_float4( INFINITY,  INFINITY,  INFINITY,  INFINITY);

    int j = s;
    for (; j + 2 <= e; j += 2) {
        int c0 = __ldg(&g_adj[j]);
        int c1 = __ldg(&g_adj[j + 1]);
        float4 f0 = *(const float4*)&feat[(size_t)c0 * D + 4 * lane];
        float4 f1 = *(const float4*)&feat[(size_t)c1 * D + 4 * lane];
        sm.x += f0.x + f1.x;  sm.y += f0.y + f1.y;
        sm.z += f0.z + f1.z;  sm.w += f0.w + f1.w;
        mx.x = fmaxf(mx.x, fmaxf(f0.x, f1.x));  mx.y = fmaxf(mx.y, fmaxf(f0.y, f1.y));
        mx.z = fmaxf(mx.z, fmaxf(f0.z, f1.z));  mx.w = fmaxf(mx.w, fmaxf(f0.w, f1.w));
        mn.x = fminf(mn.x, fminf(f0.x, f1.x));  mn.y = fminf(mn.y, fminf(f0.y, f1.y));
        mn.z = fminf(mn.z, fminf(f0.z, f1.z));  mn.w = fminf(mn.w, fminf(f0.w, f1.w));
    }
    if (j < e) {
        int c0 = __ldg(&g_adj[j]);
        float4 f0 = *(const float4*)&feat[(size_t)c0 * D + 4 * lane];
        sm.x += f0.x;  sm.y += f0.y;  sm.z += f0.z;  sm.w += f0.w;
        mx.x = fmaxf(mx.x, f0.x);  mx.y = fmaxf(mx.y, f0.y);
        mx.z = fmaxf(mx.z, f0.z);  mx.w = fmaxf(mx.w, f0.w);
        mn.x = fminf(mn.x, f0.x);  mn.y = fminf(mn.y, f0.y);
        mn.z = fminf(mn.z, f0.z);  mn.w = fminf(mn.w, f0.w);
    }
    if (e == s) {
        mx = make_float4(0.f, 0.f, 0.f, 0.f);
        mn = make_float4(0.f, 0.f, 0.f, 0.f);
    }

    float* cb = &g_comb[(size_t)node * KDIM];
    *(float4*)&cb[        4 * lane] = sm;
    *(float4*)&cb[ D  +   4 * lane] = mx;
    *(float4*)&cb[2*D +   4 * lane] = mn;
}

// ---------------- MLP GEMM with packed f32x2 FMA ----------------

__device__ __forceinline__ u64 pack2(float lo, float hi) {
    u64 r; asm("mov.b64 %0, {%1, %2};" : "=l"(r) : "f"(lo), "f"(hi)); return r;
}
__device__ __forceinline__ void ffma2(u64& d, u64 a, u64 b) {
    asm("fma.rn.f32x2 %0, %1, %2, %0;" : "+l"(d) : "l"(a), "l"(b));
}
__device__ __forceinline__ float2 unpack2(u64 v) {
    float2 f; asm("mov.b64 {%0, %1}, %2;" : "=f"(f.x), "=f"(f.y) : "l"(v)); return f;
}

#define BM 128
#define BK 16
#define BN 64

__global__ __launch_bounds__(256) void mlp_gemm_kernel(
    const float* __restrict__ Wg,     // [192,64]
    const float* __restrict__ bg,     // [64]
    float* __restrict__ out, int n)
{
    __shared__ float As[BK][BM];
    __shared__ float Bs[BK][BN];

    const float* __restrict__ A = g_comb;

    int tid = threadIdx.x;
    int block_m = blockIdx.x * BM;
    int tx = tid & 15;                // 4 output cols
    int ty = tid >> 4;                // 8 output rows (4 row-pairs)

    int a_row  = tid >> 2;
    int a_col4 = (tid & 3) * 4;
    int b_row  = tid >> 4;
    int b_col4 = (tid & 15) * 4;

    u64 acc[4][4];                    // [row-pair][col] packed f32x2
    #pragma unroll
    for (int i = 0; i < 4; i++)
        #pragma unroll
        for (int j = 0; j < 4; j++) acc[i][j] = 0ull;

    for (int k0 = 0; k0 < KDIM; k0 += BK) {
        #pragma unroll
        for (int r = 0; r < 2; r++) {
            int m  = a_row + r * 64;
            int gm = block_m + m;
            float4 v = make_float4(0.f, 0.f, 0.f, 0.f);
            if (gm < n) v = *(const float4*)&A[(size_t)gm * KDIM + k0 + a_col4];
            As[a_col4 + 0][m] = v.x;
            As[a_col4 + 1][m] = v.y;
            As[a_col4 + 2][m] = v.z;
            As[a_col4 + 3][m] = v.w;
        }
        *(float4*)&Bs[b_row][b_col4] =
            *(const float4*)&Wg[(size_t)(k0 + b_row) * BN + b_col4];
        __syncthreads();

        #pragma unroll
        for (int k = 0; k < BK; k++) {
            u64 ra[4];
            #pragma unroll
            for (int i = 0; i < 4; i++)
                ra[i] = *(const u64*)&As[k][ty * 8 + 2 * i];   // LDS.64, row pair
            float4 rbv = *(const float4*)&Bs[k][tx * 4];
            u64 rb[4];
            rb[0] = pack2(rbv.x, rbv.x);
            rb[1] = pack2(rbv.y, rbv.y);
            rb[2] = pack2(rbv.z, rbv.z);
            rb[3] = pack2(rbv.w, rbv.w);
            #pragma unroll
            for (int i = 0; i < 4; i++)
                #pragma unroll
                for (int j = 0; j < 4; j++)
                    ffma2(acc[i][j], ra[i], rb[j]);
        }
        __syncthreads();
    }

    float4 bv = *(const float4*)&bg[tx * 4];
    #pragma unroll
    for (int i = 0; i < 4; i++) {
        float2 c0 = unpack2(acc[i][0]);
        float2 c1 = unpack2(acc[i][1]);
        float2 c2 = unpack2(acc[i][2]);
        float2 c3 = unpack2(acc[i][3]);
        int gm0 = block_m + ty * 8 + 2 * i;
        if (gm0 < n) {
            float4 o;
            o.x = tanhf(c0.x + bv.x); o.y = tanhf(c1.x + bv.y);
            o.z = tanhf(c2.x + bv.z); o.w = tanhf(c3.x + bv.w);
            *(float4*)&out[(size_t)gm0 * OUTC + tx * 4] = o;
        }
        if (gm0 + 1 < n) {
            float4 o;
            o.x = tanhf(c0.y + bv.x); o.y = tanhf(c1.y + bv.y);
            o.z = tanhf(c2.y + bv.z); o.w = tanhf(c3.y + bv.w);
            *(float4*)&out[(size_t)(gm0 + 1) * OUTC + tx * 4] = o;
        }
    }
}

// ---------------- launch ----------------

extern "C" void kernel_launch(void* const* d_in, const int* in_sizes, int n_in,
                              void* d_out, int out_size) {
    const int*   row  = (const int*)d_in[0];
    const int*   col  = (const int*)d_in[1];
    const float* feat = (const float*)d_in[2];
    const float* W    = (const float*)d_in[3];
    const float* b    = (const float*)d_in[4];
    float* out = (float*)d_out;

    int E = in_sizes[0];
    int N = in_sizes[2] / D;
    int nb = (N + SCAN_B - 1) / SCAN_B;

    zero_cnt_kernel<<<(N + 255) / 256, 256>>>(N);
    hist_kernel<<<(E + 255) / 256, 256>>>(row, E);
    scan_partial_kernel<<<nb, SCAN_B>>>(N);
    scan_bsums_kernel<<<1, 256>>>(nb);
    scan_add_kernel<<<nb, SCAN_B>>>(N);
    scatter_kernel<<<(E + 255) / 256, 256>>>(row, col, E);
    aggregate_kernel<<<(N * 16 + 255) / 256, 256>>>(feat, N);
    mlp_gemm_kernel<<<(N + BM - 1) / BM, 256>>>(W, b, out, N);
}